// round 2
// baseline (speedup 1.0000x reference)
#include <cuda_runtime.h>

#define BB   32
#define DIMC 512
#define CC   128
#define WSZ  14
#define NN   196
#define NHD  4
#define HD   32
#define HIN  56

// Scratch (device globals; no runtime allocation)
__device__ float g_t[BB * NN * CC];        // tokens after conv/BN/ReLU6  [B][N][C]
__device__ float g_q[BB * NHD * NN * HD];  // [B][H][N][D] (pre-scaled)
__device__ float g_k[BB * NHD * NN * HD];
__device__ float g_v[BB * NHD * NN * HD];
__device__ float g_o[BB * NN * CC];        // attention output [B][N][C]
__device__ float g_p[BB * CC * NN];        // proj output [B][C][N]
__device__ float g_o14[BB * DIMC * NN];    // 1x1-conv output [B][512][N]

// ---------------------------------------------------------------------------
// K1: grouped conv 4x4 s4 + BN(eval) + ReLU6 -> g_t [B][N][C]
// grid (C, B), block 196 (one thread per output pixel)
// ---------------------------------------------------------------------------
__global__ void conv_kernel(const float* __restrict__ x,
                            const float* __restrict__ cw,
                            const float* __restrict__ cb,
                            const float* __restrict__ gamma,
                            const float* __restrict__ beta,
                            const float* __restrict__ mean,
                            const float* __restrict__ var)
{
    int c = blockIdx.x, b = blockIdx.y;
    int n = threadIdx.x;                 // 0..195
    int oh = n / WSZ, ow = n % WSZ;

    __shared__ float ws[64];
    if (n < 64) ws[n] = cw[c * 64 + n];
    __syncthreads();

    float acc = cb[c];
    const float* xb = x + ((size_t)b * DIMC) * HIN * HIN;
#pragma unroll
    for (int i = 0; i < 4; i++) {
        const float* xp = xb + (size_t)(4 * c + i) * HIN * HIN + (4 * oh) * HIN + 4 * ow;
#pragma unroll
        for (int kh = 0; kh < 4; kh++) {
            float4 v = *(const float4*)(xp + kh * HIN);
            const float* wp = ws + i * 16 + kh * 4;
            acc += v.x * wp[0] + v.y * wp[1] + v.z * wp[2] + v.w * wp[3];
        }
    }
    float sc = gamma[c] * rsqrtf(var[c] + 1e-5f);
    acc = acc * sc + (beta[c] - mean[c] * sc);
    acc = fminf(fmaxf(acc, 0.0f), 6.0f);
    g_t[((size_t)b * NN + n) * CC + c] = acc;
}

// ---------------------------------------------------------------------------
// K2: qkv = t @ qkv_w^T, split into q/k/v [B][H][N][D], q pre-scaled by HD^-0.5
// grid (7, B), block 384 (thread = output column j), 28-row tile
// ---------------------------------------------------------------------------
__global__ void qkv_kernel(const float* __restrict__ qkvw)
{
    int b = blockIdx.y;
    int n0 = blockIdx.x * 28;
    int j = threadIdx.x;   // 0..383

    __shared__ float ts[28][CC];
    for (int idx = j; idx < 28 * CC; idx += 384)
        ts[idx / CC][idx % CC] = g_t[((size_t)b * NN + n0 + idx / CC) * CC + idx % CC];
    __syncthreads();

    float acc[28];
#pragma unroll
    for (int r = 0; r < 28; r++) acc[r] = 0.0f;

    const float* wr = qkvw + (size_t)j * CC;
    for (int c = 0; c < CC; c++) {
        float wv = wr[c];
#pragma unroll
        for (int r = 0; r < 28; r++) acc[r] += ts[r][c] * wv;
    }

    int s = j / CC;               // 0=q,1=k,2=v
    int h = (j % CC) / HD;
    int d = j % HD;
    float scale = (s == 0) ? 0.17677669529663687f : 1.0f;
    float* dst = (s == 0) ? g_q : ((s == 1) ? g_k : g_v);
#pragma unroll
    for (int r = 0; r < 28; r++)
        dst[(((size_t)b * NHD + h) * NN + (n0 + r)) * HD + d] = acc[r] * scale;
}

// ---------------------------------------------------------------------------
// K3: attention per (b, head). 196 threads = one per query.
// Online softmax with 4-key groups (single rescale per group).
// grid (B*NH), block 196
// ---------------------------------------------------------------------------
__global__ void attn_kernel(const float* __restrict__ rpb)
{
    int bh = blockIdx.x;
    int b = bh / NHD, h = bh % NHD;
    int n = threadIdx.x;            // query index 0..195
    int r1 = n / WSZ, c1 = n % WSZ;

    __shared__ float ks[28][HD];
    __shared__ float vs[28][HD];
    __shared__ float rpb_s[729];    // (2*14-1)^2

    for (int i = n; i < 729; i += NN) rpb_s[i] = rpb[i * NHD + h];

    float qr[HD];
    const float* qp = g_q + (((size_t)b * NHD + h) * NN + n) * HD;
#pragma unroll
    for (int d = 0; d < HD; d++) qr[d] = qp[d];

    float mx = -1e30f, sum = 0.0f;
    float acc[HD];
#pragma unroll
    for (int d = 0; d < HD; d++) acc[d] = 0.0f;

    const float* kb = g_k + ((size_t)b * NHD + h) * NN * HD;
    const float* vb = g_v + ((size_t)b * NHD + h) * NN * HD;

    for (int ch = 0; ch < 7; ch++) {          // 7 chunks of 28 keys
        __syncthreads();
        for (int idx = n; idx < 28 * HD; idx += NN) {
            ks[idx / HD][idx % HD] = kb[(size_t)ch * 28 * HD + idx];
            vs[idx / HD][idx % HD] = vb[(size_t)ch * 28 * HD + idx];
        }
        __syncthreads();

        for (int g = 0; g < 7; g++) {         // groups of 4 keys
            int m0 = g * 4;
            float s0 = 0.f, s1 = 0.f, s2 = 0.f, s3 = 0.f;
#pragma unroll
            for (int d = 0; d < HD; d++) {
                float q = qr[d];
                s0 += q * ks[m0 + 0][d];
                s1 += q * ks[m0 + 1][d];
                s2 += q * ks[m0 + 2][d];
                s3 += q * ks[m0 + 3][d];
            }
            int mg = ch * 28 + m0;
#pragma unroll
            for (int t = 0; t < 4; t++) {
                int m = mg + t;
                int r2 = m / WSZ, c2 = m % WSZ;
                float bias = rpb_s[(r1 - r2 + 13) * 27 + (c1 - c2 + 13)];
                if (t == 0) s0 += bias;
                else if (t == 1) s1 += bias;
                else if (t == 2) s2 += bias;
                else s3 += bias;
            }
            float nm = fmaxf(fmaxf(fmaxf(s0, s1), fmaxf(s2, s3)), mx);
            float corr = __expf(mx - nm);
            float p0 = __expf(s0 - nm);
            float p1 = __expf(s1 - nm);
            float p2 = __expf(s2 - nm);
            float p3 = __expf(s3 - nm);
            mx = nm;
            sum = sum * corr + (p0 + p1) + (p2 + p3);
#pragma unroll
            for (int d = 0; d < HD; d++)
                acc[d] = acc[d] * corr + p0 * vs[m0 + 0][d] + p1 * vs[m0 + 1][d]
                                       + p2 * vs[m0 + 2][d] + p3 * vs[m0 + 3][d];
        }
    }

    float inv = 1.0f / sum;
    float* op = g_o + ((size_t)b * NN + n) * CC + h * HD;
#pragma unroll
    for (int d = 0; d < HD; d++) op[d] = acc[d] * inv;
}

// ---------------------------------------------------------------------------
// K4: proj = o @ proj_w^T + proj_b -> g_p [B][C][N]
// grid (7, B), block 128
// ---------------------------------------------------------------------------
__global__ void proj_kernel(const float* __restrict__ pw, const float* __restrict__ pb)
{
    int b = blockIdx.y;
    int n0 = blockIdx.x * 28;
    int j = threadIdx.x;   // 0..127

    __shared__ float os[28][CC];
    for (int idx = j; idx < 28 * CC; idx += 128)
        os[idx / CC][idx % CC] = g_o[((size_t)b * NN + n0 + idx / CC) * CC + idx % CC];
    __syncthreads();

    float acc[28];
#pragma unroll
    for (int r = 0; r < 28; r++) acc[r] = pb[j];

    const float* wr = pw + (size_t)j * CC;
    for (int c = 0; c < CC; c++) {
        float wv = wr[c];
#pragma unroll
        for (int r = 0; r < 28; r++) acc[r] += os[r][c] * wv;
    }
#pragma unroll
    for (int r = 0; r < 28; r++)
        g_p[((size_t)b * CC + j) * NN + n0 + r] = acc[r];
}

// ---------------------------------------------------------------------------
// K5: 1x1 conv to 512 channels: g_o14[b][oc][n] = sum_c w[oc][c]*g_p[b][c][n] + bias
// grid (16, B) (32 oc per block), block 196 (thread = token n)
// ---------------------------------------------------------------------------
__global__ void convout_kernel(const float* __restrict__ cw, const float* __restrict__ cb)
{
    int b = blockIdx.y;
    int oc0 = blockIdx.x * 32;
    int n = threadIdx.x;   // 0..195

    __shared__ float ws[32][CC];   // 16KB
    for (int idx = n; idx < 32 * CC; idx += NN)
        ws[idx / CC][idx % CC] = cw[(size_t)(oc0 + idx / CC) * CC + idx % CC];
    __syncthreads();

    float acc[32];
#pragma unroll
    for (int k = 0; k < 32; k++) acc[k] = cb[oc0 + k];

    const float* pbase = g_p + (size_t)b * CC * NN;
    for (int c = 0; c < CC; c++) {
        float pv = pbase[(size_t)c * NN + n];
#pragma unroll
        for (int k = 0; k < 32; k++) acc[k] += pv * ws[k][c];
    }
#pragma unroll
    for (int k = 0; k < 32; k++)
        g_o14[((size_t)b * DIMC + oc0 + k) * NN + n] = acc[k];
}

// ---------------------------------------------------------------------------
// K6: bilinear x4 upsample (align_corners=True), float4 coalesced stores
// grid (DIM, B), block 256
// ---------------------------------------------------------------------------
__global__ void upsample_kernel(float* __restrict__ out)
{
    int c = blockIdx.x;    // 0..511
    int b = blockIdx.y;
    int t = threadIdx.x;

    __shared__ float src[NN];
    __shared__ int   lo_s[HIN];
    __shared__ float w_s[HIN];

    if (t < NN) src[t] = g_o14[((size_t)b * DIMC + c) * NN + t];
    if (t < HIN) {
        float s = (float)(t * 13) / 55.0f;   // exact for integer results
        int lo = (int)s;
        lo_s[t] = lo;
        w_s[t] = s - (float)lo;
    }
    __syncthreads();

    float4* ob = (float4*)(out + ((size_t)b * DIMC + c) * HIN * HIN);
    for (int i = t; i < HIN * HIN / 4; i += 256) {   // 784 float4's
        int O = i / 14;
        int p0 = (i % 14) * 4;
        int lr = lo_s[O];
        int hr = min(lr + 1, 13);
        float wr = w_s[O];
        float4 res;
        float vals[4];
#pragma unroll
        for (int k = 0; k < 4; k++) {
            int P = p0 + k;
            int lc = lo_s[P];
            int hc = min(lc + 1, 13);
            float wc = w_s[P];
            float a = src[lr * WSZ + lc] * (1.0f - wc) + src[lr * WSZ + hc] * wc;
            float bb = src[hr * WSZ + lc] * (1.0f - wc) + src[hr * WSZ + hc] * wc;
            vals[k] = a * (1.0f - wr) + bb * wr;
        }
        res.x = vals[0]; res.y = vals[1]; res.z = vals[2]; res.w = vals[3];
        ob[i] = res;
    }
}

// ---------------------------------------------------------------------------
extern "C" void kernel_launch(void* const* d_in, const int* in_sizes, int n_in,
                              void* d_out, int out_size)
{
    (void)in_sizes; (void)n_in; (void)out_size;
    const float* x        = (const float*)d_in[0];
    const float* conv_w   = (const float*)d_in[1];
    const float* conv_b   = (const float*)d_in[2];
    const float* bn_gamma = (const float*)d_in[3];
    const float* bn_beta  = (const float*)d_in[4];
    const float* bn_mean  = (const float*)d_in[5];
    const float* bn_var   = (const float*)d_in[6];
    const float* qkv_w    = (const float*)d_in[7];
    const float* proj_w   = (const float*)d_in[8];
    const float* proj_b   = (const float*)d_in[9];
    const float* rpb      = (const float*)d_in[10];
    const float* cvo_w    = (const float*)d_in[11];
    const float* cvo_b    = (const float*)d_in[12];
    float* out = (float*)d_out;

    conv_kernel<<<dim3(CC, BB), 196>>>(x, conv_w, conv_b, bn_gamma, bn_beta, bn_mean, bn_var);
    qkv_kernel<<<dim3(7, BB), 384>>>(qkv_w);
    attn_kernel<<<BB * NHD, NN>>>(rpb);
    proj_kernel<<<dim3(7, BB), 128>>>(proj_w, proj_b);
    convout_kernel<<<dim3(16, BB), NN>>>(cvo_w, cvo_b);
    upsample_kernel<<<dim3(DIMC, BB), 256>>>(out);
}

// round 4
// speedup vs baseline: 1.4403x; 1.4403x over previous
#include <cuda_runtime.h>

#define BB   32
#define DIMC 512
#define CC   128
#define WSZ  14
#define NN   196
#define NHD  4
#define HD   32
#define HIN  56

// Scratch (device globals; no runtime allocation)
__device__ float g_t[BB * NN * CC];        // tokens after conv/BN/ReLU6  [B][N][C]
__device__ float g_q[BB * NHD * NN * HD];  // [B][H][N][D] (pre-scaled via wT)
__device__ float g_k[BB * NHD * NN * HD];
__device__ float g_v[BB * NHD * NN * HD];
__device__ float g_ot[BB * CC * NN];       // attention output TRANSPOSED [B][C][N]
__device__ float g_wf[DIMC * CC];          // fused convout@proj weight [512][128]
__device__ float g_bf[DIMC];               // fused bias
__device__ float g_wqkvT[CC * 3 * CC];     // qkv weight transposed [c][j], q rows pre-scaled

// ---------------------------------------------------------------------------
// K0a: Wf = convout_w @ proj_w ; bf = convout_w @ proj_b + convout_b
// grid 512, block 128
// ---------------------------------------------------------------------------
__global__ void fuse_weights_kernel(const float* __restrict__ cw,
                                    const float* __restrict__ cb,
                                    const float* __restrict__ pw,
                                    const float* __restrict__ pb)
{
    int oc = blockIdx.x;
    int c  = threadIdx.x;
    __shared__ float row[CC];
    __shared__ float red[CC];
    row[c] = cw[oc * CC + c];
    __syncthreads();
    float acc = 0.0f;
    for (int k = 0; k < CC; k++) acc += row[k] * pw[k * CC + c];
    g_wf[oc * CC + c] = acc;
    red[c] = row[c] * pb[c];
    __syncthreads();
    for (int s = 64; s > 0; s >>= 1) {
        if (c < s) red[c] += red[c + s];
        __syncthreads();
    }
    if (c == 0) g_bf[oc] = red[0] + cb[oc];
}

// ---------------------------------------------------------------------------
// K0b: transpose qkv_w [384][128] -> [128][384], pre-scale q rows by HD^-0.5
// grid 128 (c), block 384 (j)
// ---------------------------------------------------------------------------
__global__ void transpose_qkv_kernel(const float* __restrict__ qkvw)
{
    int c = blockIdx.x;
    int j = threadIdx.x;
    float v = qkvw[j * CC + c];
    if (j < CC) v *= 0.17677669529663687f;
    g_wqkvT[c * 384 + j] = v;
}

// ---------------------------------------------------------------------------
// K1: grouped conv 4x4 s4 + BN(eval) + ReLU6 -> g_t [B][N][C]
// grid (C, B), block 196
// ---------------------------------------------------------------------------
__global__ void conv_kernel(const float* __restrict__ x,
                            const float* __restrict__ cw,
                            const float* __restrict__ cb,
                            const float* __restrict__ gamma,
                            const float* __restrict__ beta,
                            const float* __restrict__ mean,
                            const float* __restrict__ var)
{
    int c = blockIdx.x, b = blockIdx.y;
    int n = threadIdx.x;
    int oh = n / WSZ, ow = n % WSZ;

    __shared__ float ws[64];
    if (n < 64) ws[n] = cw[c * 64 + n];
    __syncthreads();

    float acc = cb[c];
    const float* xb = x + ((size_t)b * DIMC) * HIN * HIN;
#pragma unroll
    for (int i = 0; i < 4; i++) {
        const float* xp = xb + (size_t)(4 * c + i) * HIN * HIN + (4 * oh) * HIN + 4 * ow;
#pragma unroll
        for (int kh = 0; kh < 4; kh++) {
            float4 v = *(const float4*)(xp + kh * HIN);
            const float* wp = ws + i * 16 + kh * 4;
            acc += v.x * wp[0] + v.y * wp[1] + v.z * wp[2] + v.w * wp[3];
        }
    }
    float sc = gamma[c] * rsqrtf(var[c] + 1e-5f);
    acc = acc * sc + (beta[c] - mean[c] * sc);
    acc = fminf(fmaxf(acc, 0.0f), 6.0f);
    g_t[((size_t)b * NN + n) * CC + c] = acc;
}

// ---------------------------------------------------------------------------
// K2: qkv = t @ wT. Block: 28 rows x 384 cols. 384 threads:
// thread = (jp pair of cols, rg half of rows), 2 cols x 14 rows in registers.
// grid (7, B)
// ---------------------------------------------------------------------------
__global__ void qkv_kernel()
{
    int b = blockIdx.y;
    int n0 = blockIdx.x * 28;
    int t = threadIdx.x;              // 0..383
    int jp = (t % 192) * 2;           // column pair base
    int rg = t / 192;                 // 0/1 -> rows rg*14..rg*14+13

    __shared__ float4 ts4[28][32];    // [row][c-quad]
    for (int idx = t; idx < 28 * 32; idx += 384) {
        int r = idx >> 5, qd = idx & 31;
        ts4[r][qd] = ((const float4*)(g_t + ((size_t)b * NN + n0 + r) * CC))[qd];
    }
    __syncthreads();

    float acc0[14], acc1[14];
#pragma unroll
    for (int r = 0; r < 14; r++) { acc0[r] = 0.0f; acc1[r] = 0.0f; }

    for (int cq = 0; cq < 32; cq++) {
        int c = cq * 4;
        float2 w0 = *(const float2*)(g_wqkvT + (size_t)(c + 0) * 384 + jp);
        float2 w1 = *(const float2*)(g_wqkvT + (size_t)(c + 1) * 384 + jp);
        float2 w2 = *(const float2*)(g_wqkvT + (size_t)(c + 2) * 384 + jp);
        float2 w3 = *(const float2*)(g_wqkvT + (size_t)(c + 3) * 384 + jp);
#pragma unroll
        for (int r = 0; r < 14; r++) {
            float4 tv = ts4[rg * 14 + r][cq];
            acc0[r] += tv.x * w0.x + tv.y * w1.x + tv.z * w2.x + tv.w * w3.x;
            acc1[r] += tv.x * w0.y + tv.y * w1.y + tv.z * w2.y + tv.w * w3.y;
        }
    }

#pragma unroll
    for (int which = 0; which < 2; which++) {
        int j = jp + which;
        int s = j / CC, rem = j % CC;
        int h = rem / HD, d = rem % HD;
        float* dst = (s == 0) ? g_q : ((s == 1) ? g_k : g_v);
        dst += (((size_t)(b * NHD + h)) * NN + n0 + rg * 14) * HD + d;
        const float* a = which ? acc1 : acc0;
#pragma unroll
        for (int r = 0; r < 14; r++) dst[r * HD] = a[r];
    }
}

// ---------------------------------------------------------------------------
// K3: attention. grid (4 q-tiles, 128 bh), block 224.
// thread = (qi = t>>2, ks = t&3): query qtile*49+qi, keys ks*49..ks*49+48.
// Online softmax per thread, 4-way state merge via shfl (lanes qi*4+ks).
// K/V staged in smem with stride-36 padding (bank-conflict-free for 4 ks groups).
// ---------------------------------------------------------------------------
#define KV_STRIDE 36
#define ATTN_SMEM ((196 * KV_STRIDE * 2 + 729) * 4)

__global__ void attn_kernel(const float* __restrict__ rpb)
{
    extern __shared__ float sm[];
    float* ks_s  = sm;                          // 196*36
    float* vs_s  = sm + 196 * KV_STRIDE;        // 196*36
    float* rpb_s = sm + 196 * KV_STRIDE * 2;    // 729

    int qt = blockIdx.x;
    int bh = blockIdx.y;          // b*4+h
    int h  = bh & 3;
    int t  = threadIdx.x;         // 0..223
    int qi = t >> 2, ks = t & 3;
    bool active = (qi < 49);
    int q = active ? (qt * 49 + qi) : 195;

    const float* kb = g_k + (size_t)bh * NN * HD;
    const float* vb = g_v + (size_t)bh * NN * HD;
    for (int idx = t; idx < 196 * 8; idx += 224) {
        int r = idx >> 3, qd = idx & 7;
        *(float4*)(ks_s + r * KV_STRIDE + qd * 4) = ((const float4*)(kb + r * HD))[qd];
        *(float4*)(vs_s + r * KV_STRIDE + qd * 4) = ((const float4*)(vb + r * HD))[qd];
    }
    for (int i = t; i < 729; i += 224) rpb_s[i] = rpb[i * NHD + h];
    __syncthreads();

    float4 q4[8];
    const float4* qp = (const float4*)(g_q + ((size_t)bh * NN + q) * HD);
#pragma unroll
    for (int i = 0; i < 8; i++) q4[i] = qp[i];
    int r1 = q / WSZ, c1 = q % WSZ;

    float mx = -1e30f, sum = 0.0f;
    float acc[32];
#pragma unroll
    for (int d = 0; d < 32; d++) acc[d] = 0.0f;

    int base_m = ks * 49;
    for (int g = 0; g < 7; g++) {
        int m0 = base_m + g * 7;
        float s[7];
#pragma unroll
        for (int u = 0; u < 7; u++) {
            const float* kr = ks_s + (m0 + u) * KV_STRIDE;
            float sv = 0.0f;
#pragma unroll
            for (int qd = 0; qd < 8; qd++) {
                float4 kv = *(const float4*)(kr + qd * 4);
                sv += q4[qd].x * kv.x + q4[qd].y * kv.y + q4[qd].z * kv.z + q4[qd].w * kv.w;
            }
            int m = m0 + u;
            int r2 = m / WSZ, c2 = m % WSZ;
            s[u] = sv + rpb_s[(r1 - r2 + 13) * 27 + (c1 - c2 + 13)];
        }
        float gm = s[0];
#pragma unroll
        for (int u = 1; u < 7; u++) gm = fmaxf(gm, s[u]);
        float nm = fmaxf(mx, gm);
        float corr = __expf(mx - nm);
        mx = nm;
        float ps = 0.0f;
#pragma unroll
        for (int u = 0; u < 7; u++) { s[u] = __expf(s[u] - nm); ps += s[u]; }
        sum = sum * corr + ps;

#pragma unroll
        for (int qd = 0; qd < 8; qd++) {
            float4 vv[7];
#pragma unroll
            for (int u = 0; u < 7; u++)
                vv[u] = *(const float4*)(vs_s + (m0 + u) * KV_STRIDE + qd * 4);
#pragma unroll
            for (int z = 0; z < 4; z++) {
                float a = acc[qd * 4 + z] * corr;
#pragma unroll
                for (int u = 0; u < 7; u++)
                    a += s[u] * ((const float*)&vv[u])[z];
                acc[qd * 4 + z] = a;
            }
        }
    }

    // merge 4 partial states across lanes (xor 1, xor 2)
#pragma unroll
    for (int off = 1; off <= 2; off <<= 1) {
        float m2 = __shfl_xor_sync(0xffffffffu, mx, off);
        float s2 = __shfl_xor_sync(0xffffffffu, sum, off);
        float nm = fmaxf(mx, m2);
        float c1 = __expf(mx - nm);
        float c2 = __expf(m2 - nm);
        sum = sum * c1 + s2 * c2;
#pragma unroll
        for (int d = 0; d < 32; d++)
            acc[d] = acc[d] * c1 + __shfl_xor_sync(0xffffffffu, acc[d], off) * c2;
        mx = nm;
    }

    if (active) {
        float inv = 1.0f / sum;
        int b = bh >> 2;
        // lane ks writes d-range [ks*8, ks*8+8) -> transposed output [b][c][n]
#pragma unroll
        for (int jj = 0; jj < 8; jj++) {
            int c = h * HD + ks * 8 + jj;
            g_ot[((size_t)b * CC + c) * NN + q] = acc[ks * 8 + jj] * inv;
        }
    }
}

// ---------------------------------------------------------------------------
// K4: fused (proj∘convout) GEMM + bilinear x4 upsample, writes d_out.
// grid (16 oc-tiles of 32, B), block 196.
// Phase A: thread (ng = t%49: 4 tokens, ocg = t/49: 8 oc) -> 32 acc regs.
// Phase B: upsample 32 channels from smem, float4 coalesced stores.
// ---------------------------------------------------------------------------
__global__ void outup_kernel(float* __restrict__ out)
{
    __shared__ float wfs[32 * CC];     // 16KB
    __shared__ float bfs[32];
    __shared__ float ms[32][NN];       // 25KB
    __shared__ int   lo_s[HIN];
    __shared__ float w_s[HIN];

    int b = blockIdx.y;
    int oc0 = blockIdx.x * 32;
    int t = threadIdx.x;               // 0..195

    for (int idx = t; idx < 32 * CC / 4; idx += 196)
        ((float4*)wfs)[idx] = ((const float4*)(g_wf + (size_t)oc0 * CC))[idx];
    if (t < 32) bfs[t] = g_bf[oc0 + t];
    if (t < HIN) {
        float s = (float)(t * 13) / 55.0f;
        int lo = (int)s;
        lo_s[t] = lo;
        w_s[t] = s - (float)lo;
    }
    __syncthreads();

    // Phase A
    int ng = t % 49, ocg = t / 49;
    int n0 = ng * 4;
    float acc[32];
#pragma unroll
    for (int i = 0; i < 32; i++) acc[i] = 0.0f;

    const float* ob = g_ot + (size_t)b * CC * NN;
    for (int c = 0; c < CC; c++) {
        float4 ov = *(const float4*)(ob + (size_t)c * NN + n0);
#pragma unroll
        for (int k = 0; k < 8; k++) {
            float w = wfs[(ocg * 8 + k) * CC + c];
            acc[k * 4 + 0] += w * ov.x;
            acc[k * 4 + 1] += w * ov.y;
            acc[k * 4 + 2] += w * ov.z;
            acc[k * 4 + 3] += w * ov.w;
        }
    }
#pragma unroll
    for (int k = 0; k < 8; k++) {
        float bv = bfs[ocg * 8 + k];
#pragma unroll
        for (int z = 0; z < 4; z++)
            ms[ocg * 8 + k][n0 + z] = acc[k * 4 + z] + bv;
    }
    __syncthreads();

    // Phase B: upsample 32 channels -> out[b][oc0..oc0+31][56][56]
    float4* obase = (float4*)(out + ((size_t)b * DIMC + oc0) * HIN * HIN);
    for (int i = t; i < 32 * 784; i += 196) {
        int ch = i / 784, pos = i % 784;
        int O = pos / 14;
        int p0 = (pos % 14) * 4;
        const float* src = ms[ch];
        int lr = lo_s[O];
        int hr = min(lr + 1, 13);
        float wr = w_s[O];
        float vals[4];
#pragma unroll
        for (int kk = 0; kk < 4; kk++) {
            int P = p0 + kk;
            int lc = lo_s[P];
            int hc = min(lc + 1, 13);
            float wc = w_s[P];
            float a  = src[lr * WSZ + lc] * (1.0f - wc) + src[lr * WSZ + hc] * wc;
            float bb = src[hr * WSZ + lc] * (1.0f - wc) + src[hr * WSZ + hc] * wc;
            vals[kk] = a * (1.0f - wr) + bb * wr;
        }
        float4 res = { vals[0], vals[1], vals[2], vals[3] };
        obase[i] = res;
    }
}

// ---------------------------------------------------------------------------
extern "C" void kernel_launch(void* const* d_in, const int* in_sizes, int n_in,
                              void* d_out, int out_size)
{
    (void)in_sizes; (void)n_in; (void)out_size;
    const float* x        = (const float*)d_in[0];
    const float* conv_w   = (const float*)d_in[1];
    const float* conv_b   = (const float*)d_in[2];
    const float* bn_gamma = (const float*)d_in[3];
    const float* bn_beta  = (const float*)d_in[4];
    const float* bn_mean  = (const float*)d_in[5];
    const float* bn_var   = (const float*)d_in[6];
    const float* qkv_w    = (const float*)d_in[7];
    const float* proj_w   = (const float*)d_in[8];
    const float* proj_b   = (const float*)d_in[9];
    const float* rpb      = (const float*)d_in[10];
    const float* cvo_w    = (const float*)d_in[11];
    const float* cvo_b    = (const float*)d_in[12];
    float* out = (float*)d_out;

    cudaFuncSetAttribute(attn_kernel, cudaFuncAttributeMaxDynamicSharedMemorySize, ATTN_SMEM);

    fuse_weights_kernel<<<DIMC, CC>>>(cvo_w, cvo_b, proj_w, proj_b);
    transpose_qkv_kernel<<<CC, 384>>>(qkv_w);
    conv_kernel<<<dim3(CC, BB), 196>>>(x, conv_w, conv_b, bn_gamma, bn_beta, bn_mean, bn_var);
    qkv_kernel<<<dim3(7, BB), 384>>>();
    attn_kernel<<<dim3(4, BB * NHD), 224, ATTN_SMEM>>>(rpb);
    outup_kernel<<<dim3(16, BB), 196>>>(out);
}

// round 5
// speedup vs baseline: 1.4790x; 1.0268x over previous
#include <cuda_runtime.h>

#define BB   32
#define DIMC 512
#define CC   128
#define WSZ  14
#define NN   196
#define NHD  4
#define HD   32
#define HIN  56

// Scratch (device globals; no runtime allocation)
__device__ float g_q[BB * NHD * NN * HD];  // [B][H][N][D] (pre-scaled via wT)
__device__ float g_k[BB * NHD * NN * HD];
__device__ float g_v[BB * NHD * NN * HD];
__device__ float g_ot[BB * CC * NN];       // attention output TRANSPOSED [B][C][N]
__device__ float g_wf[DIMC * CC];          // fused convout@proj weight [512][128]
__device__ float g_bf[DIMC];               // fused bias
__device__ float g_wqkvT[CC * 3 * CC];     // qkv weight transposed [c][j], q rows pre-scaled

// ---------------------------------------------------------------------------
// K0: prep. blocks 0..511: Wf = convout_w @ proj_w, bf = convout_w@proj_b + cb
//          blocks 512..639: transpose qkv_w -> [c][j], q rows pre-scaled
// grid 640, block 384
// ---------------------------------------------------------------------------
__global__ void prep_kernel(const float* __restrict__ cw,
                            const float* __restrict__ cb,
                            const float* __restrict__ pw,
                            const float* __restrict__ pb,
                            const float* __restrict__ qkvw)
{
    int t = threadIdx.x;
    if (blockIdx.x < DIMC) {
        int oc = blockIdx.x;
        __shared__ float row[CC];
        __shared__ float red[CC];
        if (t < CC) row[t] = cw[oc * CC + t];
        __syncthreads();
        if (t < CC) {
            float acc = 0.0f;
            for (int k = 0; k < CC; k++) acc += row[k] * pw[k * CC + t];
            g_wf[oc * CC + t] = acc;
            red[t] = row[t] * pb[t];
        }
        __syncthreads();
        for (int s = 64; s > 0; s >>= 1) {
            if (t < s) red[t] += red[t + s];
            __syncthreads();
        }
        if (t == 0) g_bf[oc] = red[0] + cb[oc];
    } else {
        int c = blockIdx.x - DIMC;      // 0..127
        float v = qkvw[t * CC + c];
        if (t < CC) v *= 0.17677669529663687f;
        g_wqkvT[c * 384 + t] = v;
    }
}

// ---------------------------------------------------------------------------
// K1: FUSED grouped conv 4x4 s4 + BN + ReLU6 + qkv GEMM.
// grid (7 token-tiles, B), block 448 (14 warps), 2 blocks/SM -> single wave.
// Phase 1: thread = (n = t%28, cl = t/28), 8 passes over c -> ts[28][132-pad]
// Phase 2: threads 0..383: (jp col-pair, rg row-half), 2 cols x 14 rows regs.
// ---------------------------------------------------------------------------
#define TS_STRIDE 132

__global__ void __launch_bounds__(448, 2)
convqkv_kernel(const float* __restrict__ x,
               const float* __restrict__ cw,
               const float* __restrict__ cb,
               const float* __restrict__ gamma,
               const float* __restrict__ beta,
               const float* __restrict__ mean,
               const float* __restrict__ var)
{
    __shared__ float ws[CC * 64];          // 32KB conv weights
    __shared__ float bnsc[CC], bnsh[CC];
    __shared__ float ts[28 * TS_STRIDE];   // token tile, padded

    int tile = blockIdx.x, b = blockIdx.y;
    int t = threadIdx.x;

    for (int idx = t; idx < CC * 64 / 4; idx += 448)
        ((float4*)ws)[idx] = ((const float4*)cw)[idx];
    if (t < CC) {
        float sc = gamma[t] * rsqrtf(var[t] + 1e-5f);
        bnsc[t] = sc;
        bnsh[t] = cb[t] * sc + beta[t] - mean[t] * sc;
    }
    __syncthreads();

    // ---- Phase 1: conv ----
    {
        int n = t % 28, cl = t / 28;       // cl 0..15
        int oh = tile * 2 + n / WSZ, ow = n % WSZ;
        const float* xb = x + (size_t)b * DIMC * HIN * HIN + (4 * oh) * HIN + 4 * ow;
#pragma unroll
        for (int p = 0; p < 8; p++) {
            int c = p * 16 + cl;
            float acc = 0.0f;
            const float* wp0 = ws + c * 64;
            const float* xc = xb + (size_t)(4 * c) * HIN * HIN;
#pragma unroll
            for (int i = 0; i < 4; i++) {
                const float* xp = xc + (size_t)i * HIN * HIN;
#pragma unroll
                for (int kh = 0; kh < 4; kh++) {
                    float4 v = *(const float4*)(xp + kh * HIN);
                    const float* wp = wp0 + i * 16 + kh * 4;
                    acc += v.x * wp[0] + v.y * wp[1] + v.z * wp[2] + v.w * wp[3];
                }
            }
            acc = acc * bnsc[c] + bnsh[c];
            ts[n * TS_STRIDE + c] = fminf(fmaxf(acc, 0.0f), 6.0f);
        }
    }
    __syncthreads();

    // ---- Phase 2: qkv GEMM (threads 0..383) ----
    if (t < 384) {
        int jp = (t % 192) * 2;
        int rg = t / 192;
        int n0 = tile * 28;

        float acc0[14], acc1[14];
#pragma unroll
        for (int r = 0; r < 14; r++) { acc0[r] = 0.0f; acc1[r] = 0.0f; }

        const float* tsb = ts + (rg * 14) * TS_STRIDE;
        for (int cq = 0; cq < 32; cq++) {
            int c = cq * 4;
            float2 w0 = *(const float2*)(g_wqkvT + (size_t)(c + 0) * 384 + jp);
            float2 w1 = *(const float2*)(g_wqkvT + (size_t)(c + 1) * 384 + jp);
            float2 w2 = *(const float2*)(g_wqkvT + (size_t)(c + 2) * 384 + jp);
            float2 w3 = *(const float2*)(g_wqkvT + (size_t)(c + 3) * 384 + jp);
#pragma unroll
            for (int r = 0; r < 14; r++) {
                float4 tv = *(const float4*)(tsb + r * TS_STRIDE + c);
                acc0[r] += tv.x * w0.x + tv.y * w1.x + tv.z * w2.x + tv.w * w3.x;
                acc1[r] += tv.x * w0.y + tv.y * w1.y + tv.z * w2.y + tv.w * w3.y;
            }
        }

#pragma unroll
        for (int which = 0; which < 2; which++) {
            int j = jp + which;
            int s = j / CC, rem = j % CC;
            int h = rem / HD, d = rem % HD;
            float* dst = (s == 0) ? g_q : ((s == 1) ? g_k : g_v);
            dst += (((size_t)(b * NHD + h)) * NN + n0 + rg * 14) * HD + d;
            const float* a = which ? acc1 : acc0;
#pragma unroll
            for (int r = 0; r < 14; r++) dst[r * HD] = a[r];
        }
    }
}

// ---------------------------------------------------------------------------
// K2: attention. grid (4 q-tiles, 128 bh), block 224.
// thread = (qi = t>>2, ks = t&3); online softmax, 4-way merge via shfl.
// ---------------------------------------------------------------------------
#define KV_STRIDE 36
#define ATTN_SMEM ((196 * KV_STRIDE * 2 + 729) * 4)

__global__ void attn_kernel(const float* __restrict__ rpb)
{
    extern __shared__ float sm[];
    float* ks_s  = sm;
    float* vs_s  = sm + 196 * KV_STRIDE;
    float* rpb_s = sm + 196 * KV_STRIDE * 2;

    int qt = blockIdx.x;
    int bh = blockIdx.y;
    int h  = bh & 3;
    int t  = threadIdx.x;
    int qi = t >> 2, ks = t & 3;
    bool active = (qi < 49);
    int q = active ? (qt * 49 + qi) : 195;

    const float* kb = g_k + (size_t)bh * NN * HD;
    const float* vb = g_v + (size_t)bh * NN * HD;
    for (int idx = t; idx < 196 * 8; idx += 224) {
        int r = idx >> 3, qd = idx & 7;
        *(float4*)(ks_s + r * KV_STRIDE + qd * 4) = ((const float4*)(kb + r * HD))[qd];
        *(float4*)(vs_s + r * KV_STRIDE + qd * 4) = ((const float4*)(vb + r * HD))[qd];
    }
    for (int i = t; i < 729; i += 224) rpb_s[i] = rpb[i * NHD + h];
    __syncthreads();

    float4 q4[8];
    const float4* qp = (const float4*)(g_q + ((size_t)bh * NN + q) * HD);
#pragma unroll
    for (int i = 0; i < 8; i++) q4[i] = qp[i];
    int r1 = q / WSZ, c1 = q % WSZ;

    float mx = -1e30f, sum = 0.0f;
    float acc[32];
#pragma unroll
    for (int d = 0; d < 32; d++) acc[d] = 0.0f;

    int base_m = ks * 49;
    for (int g = 0; g < 7; g++) {
        int m0 = base_m + g * 7;
        float s[7];
#pragma unroll
        for (int u = 0; u < 7; u++) {
            const float* kr = ks_s + (m0 + u) * KV_STRIDE;
            float sv = 0.0f;
#pragma unroll
            for (int qd = 0; qd < 8; qd++) {
                float4 kv = *(const float4*)(kr + qd * 4);
                sv += q4[qd].x * kv.x + q4[qd].y * kv.y + q4[qd].z * kv.z + q4[qd].w * kv.w;
            }
            int m = m0 + u;
            int r2 = m / WSZ, c2 = m % WSZ;
            s[u] = sv + rpb_s[(r1 - r2 + 13) * 27 + (c1 - c2 + 13)];
        }
        float gm = s[0];
#pragma unroll
        for (int u = 1; u < 7; u++) gm = fmaxf(gm, s[u]);
        float nm = fmaxf(mx, gm);
        float corr = __expf(mx - nm);
        mx = nm;
        float ps = 0.0f;
#pragma unroll
        for (int u = 0; u < 7; u++) { s[u] = __expf(s[u] - nm); ps += s[u]; }
        sum = sum * corr + ps;

#pragma unroll
        for (int qd = 0; qd < 8; qd++) {
            float4 vv[7];
#pragma unroll
            for (int u = 0; u < 7; u++)
                vv[u] = *(const float4*)(vs_s + (m0 + u) * KV_STRIDE + qd * 4);
#pragma unroll
            for (int z = 0; z < 4; z++) {
                float a = acc[qd * 4 + z] * corr;
#pragma unroll
                for (int u = 0; u < 7; u++)
                    a += s[u] * ((const float*)&vv[u])[z];
                acc[qd * 4 + z] = a;
            }
        }
    }

#pragma unroll
    for (int off = 1; off <= 2; off <<= 1) {
        float m2 = __shfl_xor_sync(0xffffffffu, mx, off);
        float s2 = __shfl_xor_sync(0xffffffffu, sum, off);
        float nm = fmaxf(mx, m2);
        float ca = __expf(mx - nm);
        float cb2 = __expf(m2 - nm);
        sum = sum * ca + s2 * cb2;
#pragma unroll
        for (int d = 0; d < 32; d++)
            acc[d] = acc[d] * ca + __shfl_xor_sync(0xffffffffu, acc[d], off) * cb2;
        mx = nm;
    }

    if (active) {
        float inv = 1.0f / sum;
        int b = bh >> 2;
#pragma unroll
        for (int jj = 0; jj < 8; jj++) {
            int c = h * HD + ks * 8 + jj;
            g_ot[((size_t)b * CC + c) * NN + q] = acc[ks * 8 + jj] * inv;
        }
    }
}

// ---------------------------------------------------------------------------
// K3: fused (proj∘convout) GEMM + bilinear x4 upsample, writes d_out.
// grid (16 oc-tiles, B), block 196.
// ---------------------------------------------------------------------------
__global__ void outup_kernel(float* __restrict__ out)
{
    __shared__ float wfs[32 * CC];
    __shared__ float bfs[32];
    __shared__ float ms[32][NN];
    __shared__ int   lo_s[HIN];
    __shared__ float w_s[HIN];

    int b = blockIdx.y;
    int oc0 = blockIdx.x * 32;
    int t = threadIdx.x;

    for (int idx = t; idx < 32 * CC / 4; idx += 196)
        ((float4*)wfs)[idx] = ((const float4*)(g_wf + (size_t)oc0 * CC))[idx];
    if (t < 32) bfs[t] = g_bf[oc0 + t];
    if (t < HIN) {
        float s = (float)(t * 13) / 55.0f;
        int lo = (int)s;
        lo_s[t] = lo;
        w_s[t] = s - (float)lo;
    }
    __syncthreads();

    int ng = t % 49, ocg = t / 49;
    int n0 = ng * 4;
    float acc[32];
#pragma unroll
    for (int i = 0; i < 32; i++) acc[i] = 0.0f;

    const float* ob = g_ot + (size_t)b * CC * NN;
    for (int c = 0; c < CC; c++) {
        float4 ov = *(const float4*)(ob + (size_t)c * NN + n0);
#pragma unroll
        for (int k = 0; k < 8; k++) {
            float w = wfs[(ocg * 8 + k) * CC + c];
            acc[k * 4 + 0] += w * ov.x;
            acc[k * 4 + 1] += w * ov.y;
            acc[k * 4 + 2] += w * ov.z;
            acc[k * 4 + 3] += w * ov.w;
        }
    }
#pragma unroll
    for (int k = 0; k < 8; k++) {
        float bv = bfs[ocg * 8 + k];
#pragma unroll
        for (int z = 0; z < 4; z++)
            ms[ocg * 8 + k][n0 + z] = acc[k * 4 + z] + bv;
    }
    __syncthreads();

    float4* obase = (float4*)(out + ((size_t)b * DIMC + oc0) * HIN * HIN);
    for (int i = t; i < 32 * 784; i += 196) {
        int ch = i / 784, pos = i % 784;
        int O = pos / 14;
        int p0 = (pos % 14) * 4;
        const float* src = ms[ch];
        int lr = lo_s[O];
        int hr = min(lr + 1, 13);
        float wr = w_s[O];
        float vals[4];
#pragma unroll
        for (int kk = 0; kk < 4; kk++) {
            int P = p0 + kk;
            int lc = lo_s[P];
            int hc = min(lc + 1, 13);
            float wc = w_s[P];
            float a  = src[lr * WSZ + lc] * (1.0f - wc) + src[lr * WSZ + hc] * wc;
            float bb = src[hr * WSZ + lc] * (1.0f - wc) + src[hr * WSZ + hc] * wc;
            vals[kk] = a * (1.0f - wr) + bb * wr;
        }
        float4 res = { vals[0], vals[1], vals[2], vals[3] };
        obase[i] = res;
    }
}

// ---------------------------------------------------------------------------
extern "C" void kernel_launch(void* const* d_in, const int* in_sizes, int n_in,
                              void* d_out, int out_size)
{
    (void)in_sizes; (void)n_in; (void)out_size;
    const float* x        = (const float*)d_in[0];
    const float* conv_w   = (const float*)d_in[1];
    const float* conv_b   = (const float*)d_in[2];
    const float* bn_gamma = (const float*)d_in[3];
    const float* bn_beta  = (const float*)d_in[4];
    const float* bn_mean  = (const float*)d_in[5];
    const float* bn_var   = (const float*)d_in[6];
    const float* qkv_w    = (const float*)d_in[7];
    const float* proj_w   = (const float*)d_in[8];
    const float* proj_b   = (const float*)d_in[9];
    const float* rpb      = (const float*)d_in[10];
    const float* cvo_w    = (const float*)d_in[11];
    const float* cvo_b    = (const float*)d_in[12];
    float* out = (float*)d_out;

    cudaFuncSetAttribute(attn_kernel, cudaFuncAttributeMaxDynamicSharedMemorySize, ATTN_SMEM);

    prep_kernel<<<DIMC + CC, 384>>>(cvo_w, cvo_b, proj_w, proj_b, qkv_w);
    convqkv_kernel<<<dim3(7, BB), 448>>>(x, conv_w, conv_b, bn_gamma, bn_beta, bn_mean, bn_var);
    attn_kernel<<<dim3(4, BB * NHD), 224, ATTN_SMEM>>>(rpb);
    outup_kernel<<<dim3(16, BB), 196>>>(out);
}